// round 11
// baseline (speedup 1.0000x reference)
#include <cuda_runtime.h>

#define NN   5000
#define TT   12
#define DAYC 8
#define FF   7
#define DIMC 96
#define NV4  1250         // float4s per adj row
#define QW   313          // float4s per quarter-row scan (ceil 1250/4)
#define QNZ  64           // max 16-float-group records per quarter (mean ~6)

// Scratch (allocation-free rule: __device__ globals)
__device__ float g_agg[NN * DIMC];    // [n][t*8+d], pre-scaled by 1/deg
__device__ float g_feat[NN * DIMC];   // his: col t*7+i ; cur: col 84+t

// ---------------------------------------------------------------------------
// Kernel 1: agg[n][t*8+d] = (1/deg_n) * sum_{adj[n,i]!=0} data[t,i,d]
// 4 warps per row (quarter scans), 256 thr = 2 rows/block.
// Scan: 8 uint4 loads in flight per lane (MLP=8), then ballots (1 per 16
// floats); records (i4base<<16)|mask16. __ldcs streams adj past L2.
// ---------------------------------------------------------------------------
__global__ void __launch_bounds__(256) agg_kernel(const float* __restrict__ adj,
                                                  const float* __restrict__ data) {
    __shared__ int   s_nz[2][4][QNZ];
    __shared__ int   s_cnt[2][4];
    __shared__ float s_part[2][4][DIMC];

    const int warp = threadIdx.x >> 5;
    const int lane = threadIdx.x & 31;
    const int r    = warp >> 2;
    const int q    = warp & 3;
    const int row  = blockIdx.x * 2 + r;
    const unsigned lt = (1u << lane) - 1u;

    const uint4* __restrict__ arow =
        reinterpret_cast<const uint4*>(adj + (long long)row * NN);
    const int i4beg = q * QW;
    const int i4end = (i4beg + QW < NV4) ? (i4beg + QW) : NV4;

    int cnt = 0;
    for (int base = i4beg; base < i4end; base += 256) {
        // 8 independent loads in flight before any ballot (MLP=8)
        uint4 v[8];
        #pragma unroll
        for (int u = 0; u < 8; u++) {
            const int i4 = base + u * 32 + lane;
            v[u] = make_uint4(0u, 0u, 0u, 0u);
            if (i4 < i4end) v[u] = __ldcs(&arow[i4]);
        }
        #pragma unroll
        for (int g = 0; g < 2; g++) {
            const uint4* vg = v + g * 4;
            const unsigned any0 = vg[0].x | vg[0].y | vg[0].z | vg[0].w;
            const unsigned any1 = vg[1].x | vg[1].y | vg[1].z | vg[1].w;
            const unsigned any2 = vg[2].x | vg[2].y | vg[2].z | vg[2].w;
            const unsigned any3 = vg[3].x | vg[3].y | vg[3].z | vg[3].w;
            const unsigned tot = any0 | any1 | any2 | any3;
            const unsigned bal = __ballot_sync(0xffffffffu, tot != 0u);
            if (tot != 0u) {
                unsigned m16 = 0u;
                #pragma unroll
                for (int u = 0; u < 4; u++) {
                    const unsigned m4 = (vg[u].x ? 1u : 0u) | (vg[u].y ? 2u : 0u)
                                      | (vg[u].z ? 4u : 0u) | (vg[u].w ? 8u : 0u);
                    m16 |= m4 << (4 * u);
                }
                const int p = cnt + __popc(bal & lt);
                if (p < QNZ) s_nz[r][q][p] = ((base + g * 128 + lane) << 16) | (int)m16;
            }
            cnt += __popc(bal);
        }
    }
    __syncwarp();
    const int nrec = (cnt < QNZ) ? cnt : QNZ;

    const int j0 = lane, j1 = lane + 32, j2 = lane + 64;
    const int o0 = (j0 >> 3) * (NN * DAYC) + (j0 & 7);
    const int o1 = (j1 >> 3) * (NN * DAYC) + (j1 & 7);
    const int o2 = (j2 >> 3) * (NN * DAYC) + (j2 & 7);
    float a0 = 0.f, a1 = 0.f, a2 = 0.f;
    int deg = 0;
    for (int k = 0; k < nrec; k++) {
        const int rec = s_nz[r][q][k];
        const int i4l = rec >> 16;
        unsigned mk = (unsigned)(rec & 0xffff);
        deg += __popc(mk);
        do {
            const int b = __ffs(mk) - 1;
            mk &= mk - 1u;
            const int elem = i4l * 4 + (b >> 2) * 128 + (b & 3);
            const int off = elem * DAYC;       // adj nonzeros are exactly 1.0
            a0 += __ldg(data + o0 + off);
            a1 += __ldg(data + o1 + off);
            a2 += __ldg(data + o2 + off);
        } while (mk);
    }
    s_part[r][q][j0] = a0;
    s_part[r][q][j1] = a1;
    s_part[r][q][j2] = a2;
    if (lane == 0) s_cnt[r][q] = deg;
    __syncthreads();

    if (q == 0) {
        const int tot = s_cnt[r][0] + s_cnt[r][1] + s_cnt[r][2] + s_cnt[r][3];
        const float scale = 1.0f / (float)((tot > 0) ? tot : 1);
        #pragma unroll
        for (int c3 = 0; c3 < 3; c3++) {
            const int c = lane + c3 * 32;
            g_agg[row * DIMC + c] = (s_part[r][0][c] + s_part[r][1][c]
                                   + s_part[r][2][c] + s_part[r][3][c]) * scale;
        }
    }
}

// ---------------------------------------------------------------------------
// Kernel 2: rec only. 128 threads = 16 nodes/block, grid 313.
// 8 lanes/node shuffle exchange (R9-verified), weights in smem, writes g_feat.
// ---------------------------------------------------------------------------
__global__ void __launch_bounds__(128) rec_kernel(const float* __restrict__ data,
                                                  const float* __restrict__ pos,
                                                  const float* __restrict__ hisW,   // (12,7,28)
                                                  const float* __restrict__ curW,   // (12,1,4)
                                                  const float* __restrict__ hw,     // (7,95)
                                                  const float* __restrict__ cw) {   // (1,12)
    __shared__ float s_hisW[TT * FF * 28];  // 2352
    __shared__ float s_curW[TT * 4];        // 48
    __shared__ float s_hw[FF * 95];         // 665
    __shared__ float s_cw[TT];              // 12

    const int tid  = threadIdx.x;
    const int warp = tid >> 5;
    const int lane = tid & 31;
    const int sub  = lane >> 3;
    const int li   = lane & 7;
    const int nl   = warp * 4 + sub;       // 0..15
    const int n    = blockIdx.x * 16 + nl;
    const bool act = (n < NN);
    const int  nc  = (act ? n : 0);

    // prefetch per-node inputs (36 independent loads in flight)
    float rawv[TT], pvv[TT], agv[TT];
    #pragma unroll
    for (int t = 0; t < TT; t++) {
        const long long base = ((long long)t * NN + nc) * DAYC + li;
        rawv[t] = __ldg(data + base);
        pvv[t]  = __ldg(pos  + base);
        agv[t]  = g_agg[nc * DIMC + t * DAYC + li];
    }

    for (int i = tid; i < TT * FF * 28; i += 128) s_hisW[i] = hisW[i];
    for (int i = tid; i < TT * 4;       i += 128) s_curW[i] = curW[i];
    for (int i = tid; i < FF * 95;      i += 128) s_hw[i]   = hw[i];
    if (tid < TT) s_cw[tid] = cw[tid];
    __syncthreads();

    float prevReg = 0.f;                   // li<7: prevH[li]; li==7: prevC
    float accAll  = 0.f;                   // li<7: accH[li];  li==7: accC
    #pragma unroll
    for (int t = 0; t < TT; t++) {
        float rj[FF], aj[FF], pj[FF];
        #pragma unroll
        for (int j = 0; j < FF; j++) {
            rj[j] = __shfl_sync(0xffffffffu, rawv[t], j, 8);
            aj[j] = __shfl_sync(0xffffffffu, agv[t],  j, 8);
            pj[j] = __shfl_sync(0xffffffffu, prevReg, j, 8);
        }
        float hv;
        if (li < 7) {
            const float* Wr = s_hisW + t * FF * 28 + li * 28;
            float s0 = 0.f, s1 = 0.f, s2 = 0.f;    // 3 partial chains (ILP)
            #pragma unroll
            for (int j = 0; j < FF; j++) {
                s0 += rj[j] * Wr[j];
                s1 += aj[j] * Wr[7 + j];
                s2 += pj[j] * Wr[21 + j];
            }
            hv = fmaxf(s0 + s1 + s2, 0.f) + pvv[t];
        } else {
            float c = rawv[t] * s_curW[t * 4 + 0] + agv[t] * s_curW[t * 4 + 1]
                    + prevReg * s_curW[t * 4 + 3];
            hv = fmaxf(c, 0.f) + pvv[t];
        }
        float hj[FF];
        #pragma unroll
        for (int j = 0; j < FF; j++)
            hj[j] = __shfl_sync(0xffffffffu, hv, j, 8);

        if (li < 7) {
            const float* hr = s_hw + li * 95 + t * FF;
            float s = 0.f;
            #pragma unroll
            for (int j = 0; j < FF; j++) s += hj[j] * hr[j];
            accAll += s;
            prevReg = fmaxf(accAll, 0.f);
            if (act) g_feat[n * DIMC + t * FF + li] = hv;
        } else {
            accAll += hv * s_cw[t];
            prevReg = fmaxf(accAll, 0.f);
            if (act) g_feat[n * DIMC + TT * FF + t] = hv;
        }
    }
}

// ---------------------------------------------------------------------------
// Kernel 3: out = relu(feat @ FW^T). 128 thr / 8 nodes / block, grid 625.
// 2 nodes per warp; feat staged in smem (coalesced float4); FW rows via
// __ldg float4 (36KB, L1-resident, reused by every warp on the SM).
// ---------------------------------------------------------------------------
__global__ void __launch_bounds__(128) final_kernel(const float* __restrict__ FW,
                                                    float* __restrict__ out) {
    __shared__ __align__(16) float s_feat[8 * DIMC];   // 3 KB
    const int tid  = threadIdx.x;
    const int warp = tid >> 5;
    const int lane = tid & 31;
    const int nb   = blockIdx.x * 8;

    // stage 8 feat rows coalesced (float4)
    {
        const float4* gf4 = reinterpret_cast<const float4*>(g_feat + nb * DIMC);
        float4* sf4 = reinterpret_cast<float4*>(s_feat);
        const int lim4 = ((NN - nb) < 8 ? (NN - nb) : 8) * (DIMC / 4);
        for (int i = tid; i < 8 * (DIMC / 4); i += 128)
            sf4[i] = (i < lim4) ? gf4[i] : make_float4(0.f, 0.f, 0.f, 0.f);
    }
    __syncthreads();

    const float4* __restrict__ FW4 = reinterpret_cast<const float4*>(FW);
    const int nl0 = warp * 2;
    float acc[2][3];
    #pragma unroll
    for (int m = 0; m < 2; m++) { acc[m][0] = acc[m][1] = acc[m][2] = 0.f; }

    #pragma unroll 4
    for (int k4 = 0; k4 < DIMC / 4; k4++) {
        const float4 w0 = __ldg(FW4 + lane * (DIMC / 4) + k4);
        const float4 w1 = __ldg(FW4 + (lane + 32) * (DIMC / 4) + k4);
        const float4 w2 = __ldg(FW4 + (lane + 64) * (DIMC / 4) + k4);
        float4 fv[2];
        #pragma unroll
        for (int m = 0; m < 2; m++)
            fv[m] = *reinterpret_cast<const float4*>(&s_feat[(nl0 + m) * DIMC + k4 * 4]);
        #pragma unroll
        for (int m = 0; m < 2; m++) {
            acc[m][0] += fv[m].x * w0.x + fv[m].y * w0.y + fv[m].z * w0.z + fv[m].w * w0.w;
            acc[m][1] += fv[m].x * w1.x + fv[m].y * w1.y + fv[m].z * w1.z + fv[m].w * w1.w;
            acc[m][2] += fv[m].x * w2.x + fv[m].y * w2.y + fv[m].z * w2.z + fv[m].w * w2.w;
        }
    }
    #pragma unroll
    for (int m = 0; m < 2; m++) {
        const int nn = nb + nl0 + m;
        if (nn < NN) {
            out[nn * DIMC + lane]      = fmaxf(acc[m][0], 0.f);
            out[nn * DIMC + lane + 32] = fmaxf(acc[m][1], 0.f);
            out[nn * DIMC + lane + 64] = fmaxf(acc[m][2], 0.f);
        }
    }
}

// ---------------------------------------------------------------------------
extern "C" void kernel_launch(void* const* d_in, const int* in_sizes, int n_in,
                              void* d_out, int out_size) {
    const float* adj  = (const float*)d_in[0];
    const float* data = (const float*)d_in[1];
    const float* pos  = (const float*)d_in[2];
    const float* hisW = (const float*)d_in[3];
    const float* curW = (const float*)d_in[4];
    const float* hw   = (const float*)d_in[5];
    const float* cw   = (const float*)d_in[6];
    const float* fw   = (const float*)d_in[7];
    float* out = (float*)d_out;

    agg_kernel<<<NN / 2, 256>>>(adj, data);
    rec_kernel<<<(NN + 15) / 16, 128>>>(data, pos, hisW, curW, hw, cw);
    final_kernel<<<(NN + 7) / 8, 128>>>(fw, out);
}

// round 14
// speedup vs baseline: 1.3082x; 1.3082x over previous
#include <cuda_runtime.h>

#define NN   5000
#define TT   12
#define DAYC 8
#define FF   7
#define DIMC 96
#define NV4  1250         // float4s per adj row
#define QW   313          // float4s per quarter-row scan (ceil 1250/4)
#define QNZ  64           // max 16-float-group records per quarter (mean ~6)

// Scratch (allocation-free rule: __device__ globals).
// Padded by 16 rows so block-granular staging loops stay mapped.
__device__ __align__(16) float g_agg[(NN + 16) * DIMC];
__device__ __align__(16) float g_feat[(NN + 16) * DIMC];

// ---------------------------------------------------------------------------
// Kernel 1 (exact R7 version — best measured): 4 warps/row quarter scans,
// one ballot per 16 floats, records (i4base<<16)|mask16, __ldcs on adj.
// ---------------------------------------------------------------------------
__global__ void __launch_bounds__(256) agg_kernel(const float* __restrict__ adj,
                                                  const float* __restrict__ data) {
    __shared__ int   s_nz[2][4][QNZ];
    __shared__ int   s_cnt[2][4];
    __shared__ float s_part[2][4][DIMC];

    const int warp = threadIdx.x >> 5;
    const int lane = threadIdx.x & 31;
    const int r    = warp >> 2;
    const int q    = warp & 3;
    const int row  = blockIdx.x * 2 + r;
    const unsigned lt = (1u << lane) - 1u;

    const uint4* __restrict__ arow =
        reinterpret_cast<const uint4*>(adj + (long long)row * NN);
    const int i4beg = q * QW;
    const int i4end = (i4beg + QW < NV4) ? (i4beg + QW) : NV4;

    int cnt = 0;
    for (int base = i4beg; base < i4end; base += 128) {
        uint4 v[4];
        #pragma unroll
        for (int u = 0; u < 4; u++) {
            const int i4 = base + u * 32 + lane;
            v[u] = make_uint4(0u, 0u, 0u, 0u);
            if (i4 < i4end) v[u] = __ldcs(&arow[i4]);
        }
        const unsigned any0 = v[0].x | v[0].y | v[0].z | v[0].w;
        const unsigned any1 = v[1].x | v[1].y | v[1].z | v[1].w;
        const unsigned any2 = v[2].x | v[2].y | v[2].z | v[2].w;
        const unsigned any3 = v[3].x | v[3].y | v[3].z | v[3].w;
        const unsigned tot = any0 | any1 | any2 | any3;
        const unsigned bal = __ballot_sync(0xffffffffu, tot != 0u);
        if (tot != 0u) {
            unsigned m16 = 0u;
            #pragma unroll
            for (int u = 0; u < 4; u++) {
                const unsigned m4 = (v[u].x ? 1u : 0u) | (v[u].y ? 2u : 0u)
                                  | (v[u].z ? 4u : 0u) | (v[u].w ? 8u : 0u);
                m16 |= m4 << (4 * u);
            }
            const int p = cnt + __popc(bal & lt);
            if (p < QNZ) s_nz[r][q][p] = ((base + lane) << 16) | (int)m16;
        }
        cnt += __popc(bal);
    }
    __syncwarp();
    const int nrec = (cnt < QNZ) ? cnt : QNZ;

    const int j0 = lane, j1 = lane + 32, j2 = lane + 64;
    const int o0 = (j0 >> 3) * (NN * DAYC) + (j0 & 7);
    const int o1 = (j1 >> 3) * (NN * DAYC) + (j1 & 7);
    const int o2 = (j2 >> 3) * (NN * DAYC) + (j2 & 7);
    float a0 = 0.f, a1 = 0.f, a2 = 0.f;
    int deg = 0;
    for (int k = 0; k < nrec; k++) {
        const int rec = s_nz[r][q][k];
        const int i4l = rec >> 16;
        unsigned mk = (unsigned)(rec & 0xffff);
        deg += __popc(mk);
        do {
            const int b = __ffs(mk) - 1;
            mk &= mk - 1u;
            const int elem = i4l * 4 + (b >> 2) * 128 + (b & 3);
            const int off = elem * DAYC;       // adj nonzeros are exactly 1.0
            a0 += __ldg(data + o0 + off);
            a1 += __ldg(data + o1 + off);
            a2 += __ldg(data + o2 + off);
        } while (mk);
    }
    s_part[r][q][j0] = a0;
    s_part[r][q][j1] = a1;
    s_part[r][q][j2] = a2;
    if (lane == 0) s_cnt[r][q] = deg;
    __syncthreads();

    if (q == 0) {
        const int tot = s_cnt[r][0] + s_cnt[r][1] + s_cnt[r][2] + s_cnt[r][3];
        const float scale = 1.0f / (float)((tot > 0) ? tot : 1);
        #pragma unroll
        for (int c3 = 0; c3 < 3; c3++) {
            const int c = lane + c3 * 32;
            g_agg[row * DIMC + c] = (s_part[r][0][c] + s_part[r][1][c]
                                   + s_part[r][2][c] + s_part[r][3][c]) * scale;
        }
    }
}

// ---------------------------------------------------------------------------
// Kernel 2: rec, ONE THREAD PER NODE. Zero exchange; all channel state in
// registers; weight reads are warp-broadcast LDS. 64 thr/block, grid 79.
// ---------------------------------------------------------------------------
__global__ void __launch_bounds__(64) rec_kernel(const float* __restrict__ data,
                                                 const float* __restrict__ pos,
                                                 const float* __restrict__ hisW,   // (12,7,28)
                                                 const float* __restrict__ curW,   // (12,1,4)
                                                 const float* __restrict__ hw,     // (7,95)
                                                 const float* __restrict__ cw) {   // (1,12)
    __shared__ float s_hisW[TT * FF * 28];  // 2352
    __shared__ float s_curW[TT * 4];        // 48
    __shared__ float s_hw[FF * 95];         // 665
    __shared__ float s_cw[TT];              // 12

    const int tid = threadIdx.x;
    for (int i = tid; i < TT * FF * 28; i += 64) s_hisW[i] = hisW[i];
    for (int i = tid; i < TT * 4;       i += 64) s_curW[i] = curW[i];
    for (int i = tid; i < FF * 95;      i += 64) s_hw[i]   = hw[i];
    if (tid < TT) s_cw[tid] = cw[tid];
    __syncthreads();

    const int n   = blockIdx.x * 64 + tid;
    const bool act = (n < NN);
    const int  nc  = act ? n : 0;

    float accH[FF]  = {0.f, 0.f, 0.f, 0.f, 0.f, 0.f, 0.f};
    float prevH[FF] = {0.f, 0.f, 0.f, 0.f, 0.f, 0.f, 0.f};
    float accC = 0.f, prevC = 0.f;

    #pragma unroll
    for (int t = 0; t < TT; t++) {
        const float4* dp = reinterpret_cast<const float4*>(data  + ((long long)t * NN + nc) * DAYC);
        const float4* pp = reinterpret_cast<const float4*>(pos   + ((long long)t * NN + nc) * DAYC);
        const float4* ap = reinterpret_cast<const float4*>(g_agg + nc * DIMC + t * DAYC);
        const float4 d0 = __ldg(dp), d1 = __ldg(dp + 1);
        const float4 p0 = __ldg(pp), p1 = __ldg(pp + 1);
        const float4 g0 = ap[0],     g1 = ap[1];
        const float raw[8] = {d0.x, d0.y, d0.z, d0.w, d1.x, d1.y, d1.z, d1.w};
        const float pv[8]  = {p0.x, p0.y, p0.z, p0.w, p1.x, p1.y, p1.z, p1.w};
        const float ag[8]  = {g0.x, g0.y, g0.z, g0.w, g1.x, g1.y, g1.z, g1.w};

        float h[FF];
        const float* Wt = s_hisW + t * FF * 28;
        #pragma unroll
        for (int i = 0; i < FF; i++) {
            const float* Wr = Wt + i * 28;
            float s0 = 0.f, s1 = 0.f, s2 = 0.f;
            #pragma unroll
            for (int j = 0; j < FF; j++) {
                s0 += raw[j]   * Wr[j];
                s1 += ag[j]    * Wr[7 + j];
                s2 += prevH[j] * Wr[21 + j];
            }
            h[i] = fmaxf(s0 + s1 + s2, 0.f) + pv[i];
        }
        float c = raw[7] * s_curW[t * 4 + 0] + ag[7] * s_curW[t * 4 + 1]
                + prevC * s_curW[t * 4 + 3];
        c = fmaxf(c, 0.f) + pv[7];

        #pragma unroll
        for (int i = 0; i < FF; i++) {
            const float* hr = s_hw + i * 95 + t * FF;
            float s = 0.f;
            #pragma unroll
            for (int j = 0; j < FF; j++) s += h[j] * hr[j];
            accH[i] += s;
            prevH[i] = fmaxf(accH[i], 0.f);
        }
        accC += c * s_cw[t];
        prevC = fmaxf(accC, 0.f);

        if (act) {
            #pragma unroll
            for (int i = 0; i < FF; i++) g_feat[n * DIMC + t * FF + i] = h[i];
            g_feat[n * DIMC + TT * FF + t] = c;
        }
    }
}

// ---------------------------------------------------------------------------
// Kernel 3: out = relu(feat @ FW^T). 128 thr / 16 nodes / block, grid 313.
// 4 nodes per warp (4 warps x 4 = 16 = nodes staged), FW chunk in registers:
// per k4 chunk 12 conflict-free FW LDS + 4 broadcast feat LDS.128 -> 48 FMA.
// Static smem: 96*97*4 + 16*96*4 = 43392 B (< 48 KB).
// ---------------------------------------------------------------------------
__global__ void __launch_bounds__(128) final_kernel(const float* __restrict__ FW,
                                                    float* __restrict__ out) {
    __shared__ float s_FW[DIMC * 97];                 // s_FW[j*97+k] = FW[j*96+k]
    __shared__ __align__(16) float s_feat[16 * DIMC]; // 6 KB
    const int tid  = threadIdx.x;
    const int warp = tid >> 5;
    const int lane = tid & 31;
    const int nb   = blockIdx.x * 16;

    for (int i = tid; i < DIMC * DIMC; i += 128) {
        const int j = i / DIMC, k = i - j * DIMC;
        s_FW[j * 97 + k] = __ldg(FW + i);
    }
    {
        // g_feat padded by 16 rows -> unconditional staging is in-bounds
        const float4* gf4 = reinterpret_cast<const float4*>(g_feat + nb * DIMC);
        float4* sf4 = reinterpret_cast<float4*>(s_feat);
        for (int i = tid; i < 16 * (DIMC / 4); i += 128)
            sf4[i] = gf4[i];
    }
    __syncthreads();

    const int nl0 = warp * 4;          // 4 warps x 4 nodes = 16 nodes
    float acc[4][3];
    #pragma unroll
    for (int m = 0; m < 4; m++) { acc[m][0] = acc[m][1] = acc[m][2] = 0.f; }

    #pragma unroll 2
    for (int k4 = 0; k4 < DIMC / 4; k4++) {
        const int k = k4 * 4;
        float f0[4], f1[4], f2[4];     // FW rows lane, lane+32, lane+64
        #pragma unroll
        for (int kk = 0; kk < 4; kk++) {
            f0[kk] = s_FW[lane * 97 + k + kk];
            f1[kk] = s_FW[(lane + 32) * 97 + k + kk];
            f2[kk] = s_FW[(lane + 64) * 97 + k + kk];
        }
        #pragma unroll
        for (int m = 0; m < 4; m++) {
            const float4 fv = *reinterpret_cast<const float4*>(
                &s_feat[(nl0 + m) * DIMC + k]);            // broadcast
            acc[m][0] += fv.x * f0[0] + fv.y * f0[1] + fv.z * f0[2] + fv.w * f0[3];
            acc[m][1] += fv.x * f1[0] + fv.y * f1[1] + fv.z * f1[2] + fv.w * f1[3];
            acc[m][2] += fv.x * f2[0] + fv.y * f2[1] + fv.z * f2[2] + fv.w * f2[3];
        }
    }
    #pragma unroll
    for (int m = 0; m < 4; m++) {
        const int nn = nb + nl0 + m;
        if (nn < NN) {
            out[nn * DIMC + lane]      = fmaxf(acc[m][0], 0.f);
            out[nn * DIMC + lane + 32] = fmaxf(acc[m][1], 0.f);
            out[nn * DIMC + lane + 64] = fmaxf(acc[m][2], 0.f);
        }
    }
}

// ---------------------------------------------------------------------------
extern "C" void kernel_launch(void* const* d_in, const int* in_sizes, int n_in,
                              void* d_out, int out_size) {
    const float* adj  = (const float*)d_in[0];
    const float* data = (const float*)d_in[1];
    const float* pos  = (const float*)d_in[2];
    const float* hisW = (const float*)d_in[3];
    const float* curW = (const float*)d_in[4];
    const float* hw   = (const float*)d_in[5];
    const float* cw   = (const float*)d_in[6];
    const float* fw   = (const float*)d_in[7];
    float* out = (float*)d_out;

    agg_kernel<<<NN / 2, 256>>>(adj, data);
    rec_kernel<<<(NN + 63) / 64, 64>>>(data, pos, hisW, curW, hw, cw);
    final_kernel<<<(NN + 15) / 16, 128>>>(fw, out);
}